// round 2
// baseline (speedup 1.0000x reference)
#include <cuda_runtime.h>
#include <cstdint>

#define NNODES_MAX 100000
#define DH 128
#define NGRAPH 512

// ---------------- scratch (static device globals; no allocation) ------------
__device__ float g_h[NNODES_MAX * DH];     // layer output h
__device__ float g_agg[NNODES_MAX * DH];   // holds h + A*h (seeded with h, atomically accumulated)
__device__ float g_pool[NGRAPH * DH];      // per-graph feature sums
__device__ float g_cnt[NGRAPH];            // per-graph node counts

// ---------------- helpers ---------------------------------------------------
__device__ __forceinline__ void red4(float* p, float4 v) {
    // vector reduction-atomic (sm_90+): no return value -> REDG, not ATOMG
    asm volatile("red.global.add.v4.f32 [%0], {%1,%2,%3,%4};"
                 :: "l"(p), "f"(v.x), "f"(v.y), "f"(v.z), "f"(v.w)
                 : "memory");
}

// ---------------- tiny kernels ----------------------------------------------
__global__ void zero_pool_kernel() {
    int i = blockIdx.x * blockDim.x + threadIdx.x;
    if (i < NGRAPH * DH) g_pool[i] = 0.f;
    if (i < NGRAPH) g_cnt[i] = 0.f;
}

__global__ void copy_to_agg(const float4* __restrict__ x, int n4) {
    int i = blockIdx.x * blockDim.x + threadIdx.x;
    if (i < n4) reinterpret_cast<float4*>(g_agg)[i] = x[i];
}

__global__ void count_kernel(const int* __restrict__ batch, int n) {
    int i = blockIdx.x * blockDim.x + threadIdx.x;
    if (i < n) atomicAdd(&g_cnt[batch[i]], 1.0f);
}

// ---------------- edge scatter: g_agg[dst] += h[src] ------------------------
// one warp per edge; lane l handles 4 floats (float4) of the 128-dim feature
template<bool FIRST>
__global__ void scatter_kernel(const float* __restrict__ x,
                               const int* __restrict__ ei, int E) {
    int w    = (blockIdx.x * blockDim.x + threadIdx.x) >> 5;
    int lane = threadIdx.x & 31;
    if (w >= E) return;
    int s = 0, d = 0;
    if (lane == 0) { s = ei[w]; d = ei[E + w]; }
    s = __shfl_sync(0xffffffffu, s, 0);
    d = __shfl_sync(0xffffffffu, d, 0);
    const float4* src = FIRST ? reinterpret_cast<const float4*>(x)
                              : reinterpret_cast<const float4*>(g_h);
    float4 v = src[s * 32 + lane];
    red4(&g_agg[d * DH + lane * 4], v);
}

// ---------------- fused GEMM: out = act( g_agg @ W^T + b ) ------------------
// C[i][j] = sum_k in[i][k] * W[j][k];  BM=64, BN=128(full), BK=32, 256 thr
// epilogue: write g_h (+ seed g_agg for next layer) or fused graph pooling
#define BM 64
#define BK 32

template<bool RELU, bool WRITE_AGG, bool POOL>
__global__ __launch_bounds__(256)
void gemm_kernel(const float* __restrict__ W, const float* __restrict__ bias,
                 const int* __restrict__ batch, int M) {
    __shared__ float As[BM][36];     // [m][k], pad to 36 (16B-aligned rows, no bank conflicts)
    __shared__ float Ws[BK][132];    // [k][j], pad to 132 (16B-aligned rows)

    const int tid = threadIdx.x;
    const int tx  = tid & 15;        // 16 col-groups * 8 cols
    const int ty  = tid >> 4;        // 16 row-groups * 4 rows
    const int rowBase = blockIdx.x * BM;

    float acc[4][8];
#pragma unroll
    for (int r = 0; r < 4; r++)
#pragma unroll
        for (int c = 0; c < 8; c++) acc[r][c] = 0.f;

    const int lr = tid >> 3;         // 0..31 load row
    const int lk = (tid & 7) * 4;    // 0,4,...,28

    for (int kc = 0; kc < DH; kc += BK) {
        // stage A (rows lr, lr+32)
#pragma unroll
        for (int p = 0; p < 2; p++) {
            int r = lr + p * 32;
            int grow = rowBase + r;
            if (grow >= M) grow = M - 1;
            float4 v = *reinterpret_cast<const float4*>(&g_agg[grow * DH + kc + lk]);
            *reinterpret_cast<float4*>(&As[r][lk]) = v;
        }
        // stage W transposed: Ws[k][j] = W[j][kc+k]
#pragma unroll
        for (int p = 0; p < 4; p++) {
            int j = lr + p * 32;
            float4 v = *reinterpret_cast<const float4*>(&W[j * DH + kc + lk]);
            Ws[lk + 0][j] = v.x; Ws[lk + 1][j] = v.y;
            Ws[lk + 2][j] = v.z; Ws[lk + 3][j] = v.w;
        }
        __syncthreads();
#pragma unroll
        for (int k = 0; k < BK; k++) {
            float4 w0 = *reinterpret_cast<const float4*>(&Ws[k][tx * 8]);
            float4 w1 = *reinterpret_cast<const float4*>(&Ws[k][tx * 8 + 4]);
            float bv[8] = {w0.x, w0.y, w0.z, w0.w, w1.x, w1.y, w1.z, w1.w};
#pragma unroll
            for (int r = 0; r < 4; r++) {
                float a = As[ty * 4 + r][k];
#pragma unroll
                for (int c = 0; c < 8; c++) acc[r][c] = fmaf(a, bv[c], acc[r][c]);
            }
        }
        __syncthreads();
    }

    float4 bia0 = *reinterpret_cast<const float4*>(&bias[tx * 8]);
    float4 bia1 = *reinterpret_cast<const float4*>(&bias[tx * 8 + 4]);
#pragma unroll
    for (int r = 0; r < 4; r++) {
        int row = rowBase + ty * 4 + r;
        if (row >= M) continue;
        float4 o0, o1;
        o0.x = acc[r][0] + bia0.x; o0.y = acc[r][1] + bia0.y;
        o0.z = acc[r][2] + bia0.z; o0.w = acc[r][3] + bia0.w;
        o1.x = acc[r][4] + bia1.x; o1.y = acc[r][5] + bia1.y;
        o1.z = acc[r][6] + bia1.z; o1.w = acc[r][7] + bia1.w;
        if (RELU) {
            o0.x = fmaxf(o0.x, 0.f); o0.y = fmaxf(o0.y, 0.f);
            o0.z = fmaxf(o0.z, 0.f); o0.w = fmaxf(o0.w, 0.f);
            o1.x = fmaxf(o1.x, 0.f); o1.y = fmaxf(o1.y, 0.f);
            o1.z = fmaxf(o1.z, 0.f); o1.w = fmaxf(o1.w, 0.f);
        }
        *reinterpret_cast<float4*>(&g_h[row * DH + tx * 8])     = o0;
        *reinterpret_cast<float4*>(&g_h[row * DH + tx * 8 + 4]) = o1;
        if (WRITE_AGG) {
            *reinterpret_cast<float4*>(&g_agg[row * DH + tx * 8])     = o0;
            *reinterpret_cast<float4*>(&g_agg[row * DH + tx * 8 + 4]) = o1;
        }
        if (POOL) {
            int b = batch[row];
            red4(&g_pool[b * DH + tx * 8],     o0);
            red4(&g_pool[b * DH + tx * 8 + 4], o1);
        }
    }
}

// ---------------- head: out[g][o] = dot(pool[g]/cnt[g], Wg[o]) + bg[o] ------
__global__ void final_kernel(const float* __restrict__ Wg,
                             const float* __restrict__ bg,
                             float* __restrict__ out) {
    int g = blockIdx.x;
    int lane = threadIdx.x;
    float4 p = reinterpret_cast<const float4*>(g_pool)[g * 32 + lane];
    float c = fmaxf(g_cnt[g], 1.0f);
#pragma unroll
    for (int o = 0; o < 10; o++) {
        float4 w = reinterpret_cast<const float4*>(Wg)[o * 32 + lane];
        float s = p.x * w.x + p.y * w.y + p.z * w.z + p.w * w.w;
#pragma unroll
        for (int off = 16; off; off >>= 1) s += __shfl_xor_sync(0xffffffffu, s, off);
        if (lane == 0) out[g * 10 + o] = s / c + bg[o];
    }
}

// ---------------- launch ----------------------------------------------------
extern "C" void kernel_launch(void* const* d_in, const int* in_sizes, int n_in,
                              void* d_out, int out_size) {
    const float* x     = (const float*)d_in[0];
    const int*   ei    = (const int*)d_in[1];      // int32 (JAX x64 disabled downcasts int64)
    const int*   batch = (const int*)d_in[2];
    const float* W0 = (const float*)d_in[3];
    const float* b0 = (const float*)d_in[4];
    const float* W1 = (const float*)d_in[5];
    const float* b1 = (const float*)d_in[6];
    const float* W2 = (const float*)d_in[7];
    const float* b2 = (const float*)d_in[8];
    const float* Wg = (const float*)d_in[9];
    const float* bg = (const float*)d_in[10];
    float* out = (float*)d_out;

    const int N = in_sizes[0] / DH;     // 100000 nodes
    const int E = in_sizes[1] / 2;      // 1600000 edges

    const int n4 = N * (DH / 4);
    const int gemm_grid = (N + BM - 1) / BM;
    const int scat_grid = (E + 7) / 8;  // 8 warps/block, 1 edge/warp

    zero_pool_kernel<<<(NGRAPH * DH + 511) / 512, 512>>>();
    count_kernel<<<(N + 255) / 256, 256>>>(batch, N);

    // layer 0: agg = x + A x ; h = relu(agg @ W0^T + b0), seed agg with h
    copy_to_agg<<<(n4 + 511) / 512, 512>>>(reinterpret_cast<const float4*>(x), n4);
    scatter_kernel<true><<<scat_grid, 256>>>(x, ei, E);
    gemm_kernel<true, true, false><<<gemm_grid, 256>>>(W0, b0, nullptr, N);

    // layer 1
    scatter_kernel<false><<<scat_grid, 256>>>(nullptr, ei, E);
    gemm_kernel<true, true, false><<<gemm_grid, 256>>>(W1, b1, nullptr, N);

    // layer 2 (no relu) fused with graph pooling
    scatter_kernel<false><<<scat_grid, 256>>>(nullptr, ei, E);
    gemm_kernel<false, false, true><<<gemm_grid, 256>>>(W2, b2, batch, N);

    final_kernel<<<NGRAPH, 32>>>(Wg, bg, out);
}

// round 3
// speedup vs baseline: 1.2703x; 1.2703x over previous
#include <cuda_runtime.h>
#include <cstdint>

#define NNODES_MAX 100000
#define EDGES_MAX  1600000
#define DH 128
#define NGRAPH 512

// ---------------- scratch (static device globals; no allocation) ------------
__device__ float g_h[NNODES_MAX * DH];       // layer output h
__device__ float g_agg[NNODES_MAX * DH];     // h + A*h (gather output)
__device__ float g_pool[NGRAPH * DH];        // per-graph feature sums
__device__ float g_cnt[NGRAPH];              // per-graph node counts
__device__ int   g_deg[NNODES_MAX];          // in-degree histogram
__device__ int   g_cur[NNODES_MAX];          // fill cursors
__device__ int   g_rowptr[NNODES_MAX + 1];   // CSR row pointers (by dst)
__device__ int   g_col[EDGES_MAX];           // CSR column indices (src nodes)

// ---------------- helpers ---------------------------------------------------
__device__ __forceinline__ void red4(float* p, float4 v) {
    asm volatile("red.global.add.v4.f32 [%0], {%1,%2,%3,%4};"
                 :: "l"(p), "f"(v.x), "f"(v.y), "f"(v.z), "f"(v.w)
                 : "memory");
}

// ---------------- init: zero pool/cnt/deg/cur --------------------------------
__global__ void init_kernel(int n) {
    int i = blockIdx.x * blockDim.x + threadIdx.x;
    if (i < NGRAPH * DH) g_pool[i] = 0.f;
    if (i < NGRAPH) g_cnt[i] = 0.f;
    if (i < n) { g_deg[i] = 0; g_cur[i] = 0; }
}

__global__ void count_kernel(const int* __restrict__ batch, int n) {
    int i = blockIdx.x * blockDim.x + threadIdx.x;
    if (i < n) atomicAdd(&g_cnt[batch[i]], 1.0f);
}

// ---------------- CSR build --------------------------------------------------
__global__ void hist_kernel(const int* __restrict__ ei, int E) {
    int i = blockIdx.x * blockDim.x + threadIdx.x;
    if (i < E) atomicAdd(&g_deg[ei[E + i]], 1);   // dst
}

// single-block exclusive scan of g_deg[0..n) into g_rowptr[0..n]
__global__ void scan_kernel(int n) {
    const int T = 1024;
    __shared__ int part[T];
    int t = threadIdx.x;
    int C = (n + T - 1) / T;
    int beg = t * C;
    int end = beg + C < n ? beg + C : n;
    int s = 0;
    for (int i = beg; i < end; i++) s += g_deg[i];
    part[t] = s;
    __syncthreads();
    for (int off = 1; off < T; off <<= 1) {
        int v = (t >= off) ? part[t - off] : 0;
        __syncthreads();
        part[t] += v;
        __syncthreads();
    }
    int run = (t == 0) ? 0 : part[t - 1];
    for (int i = beg; i < end; i++) { g_rowptr[i] = run; run += g_deg[i]; }
    if (t == 0) g_rowptr[n] = part[T - 1];
}

__global__ void fill_kernel(const int* __restrict__ ei, int E) {
    int i = blockIdx.x * blockDim.x + threadIdx.x;
    if (i >= E) return;
    int s = ei[i];
    int d = ei[E + i];
    int pos = g_rowptr[d] + atomicAdd(&g_cur[d], 1);
    g_col[pos] = s;
}

// ---------------- gather: g_agg[n] = src[n] + sum_{j in N(n)} src[j] ---------
// one warp per node; lane handles one float4 (4 features)
template<bool FIRST>
__global__ void gather_kernel(const float* __restrict__ x, int N) {
    int w    = (blockIdx.x * blockDim.x + threadIdx.x) >> 5;
    int lane = threadIdx.x & 31;
    if (w >= N) return;
    const float4* src = FIRST ? reinterpret_cast<const float4*>(x)
                              : reinterpret_cast<const float4*>(g_h);
    int beg = g_rowptr[w];
    int end = g_rowptr[w + 1];
    float4 acc = src[w * 32 + lane];                      // seed: own features
    for (int base = beg; base < end; base += 32) {
        int idx = (base + lane < end) ? g_col[base + lane] : 0;
        int cnt = end - base; if (cnt > 32) cnt = 32;
#pragma unroll 4
        for (int j = 0; j < cnt; j++) {
            int s = __shfl_sync(0xffffffffu, idx, j);
            float4 v = src[s * 32 + lane];
            acc.x += v.x; acc.y += v.y; acc.z += v.z; acc.w += v.w;
        }
    }
    reinterpret_cast<float4*>(g_agg)[w * 32 + lane] = acc;
}

// ---------------- fused GEMM: out = act( g_agg @ W^T + b ) -------------------
// C[i][j] = sum_k A[i][k] * W[j][k];  BM=128, BN=128, BK=32, 256 threads, 8x8
#define GBM 128
#define GBK 32

template<bool RELU, bool POOL>
__global__ __launch_bounds__(256)
void gemm_kernel(const float* __restrict__ W, const float* __restrict__ bias,
                 const int* __restrict__ batch, int M) {
    __shared__ float As[GBK][GBM + 4];   // transposed: As[k][m]
    __shared__ float Ws[GBK][GBM + 4];   // transposed: Ws[k][j]

    const int tid = threadIdx.x;
    const int tx  = tid & 15;            // 16 col-groups * 8 cols
    const int ty  = tid >> 4;            // 16 row-groups * 8 rows
    const int rowBase = blockIdx.x * GBM;

    float acc[8][8];
#pragma unroll
    for (int r = 0; r < 8; r++)
#pragma unroll
        for (int c = 0; c < 8; c++) acc[r][c] = 0.f;

    const int lr = tid >> 3;             // 0..31
    const int lk = (tid & 7) * 4;        // 0,4,...,28

#pragma unroll
    for (int kc = 0; kc < DH; kc += GBK) {
        // stage A tile (128 rows x 32 cols), transposed into As[k][m]
#pragma unroll
        for (int p = 0; p < 4; p++) {
            int r = lr + p * 32;
            int grow = rowBase + r;
            if (grow >= M) grow = M - 1;
            float4 v = *reinterpret_cast<const float4*>(&g_agg[grow * DH + kc + lk]);
            As[lk + 0][r] = v.x; As[lk + 1][r] = v.y;
            As[lk + 2][r] = v.z; As[lk + 3][r] = v.w;
        }
        // stage W tile: Ws[k][j] = W[j][kc+k]
#pragma unroll
        for (int p = 0; p < 4; p++) {
            int j = lr + p * 32;
            float4 v = *reinterpret_cast<const float4*>(&W[j * DH + kc + lk]);
            Ws[lk + 0][j] = v.x; Ws[lk + 1][j] = v.y;
            Ws[lk + 2][j] = v.z; Ws[lk + 3][j] = v.w;
        }
        __syncthreads();
#pragma unroll
        for (int k = 0; k < GBK; k++) {
            float4 a0 = *reinterpret_cast<const float4*>(&As[k][ty * 8]);
            float4 a1 = *reinterpret_cast<const float4*>(&As[k][ty * 8 + 4]);
            float4 w0 = *reinterpret_cast<const float4*>(&Ws[k][tx * 8]);
            float4 w1 = *reinterpret_cast<const float4*>(&Ws[k][tx * 8 + 4]);
            float av[8] = {a0.x, a0.y, a0.z, a0.w, a1.x, a1.y, a1.z, a1.w};
            float wv[8] = {w0.x, w0.y, w0.z, w0.w, w1.x, w1.y, w1.z, w1.w};
#pragma unroll
            for (int r = 0; r < 8; r++)
#pragma unroll
                for (int c = 0; c < 8; c++)
                    acc[r][c] = fmaf(av[r], wv[c], acc[r][c]);
        }
        __syncthreads();
    }

    float4 bia0 = *reinterpret_cast<const float4*>(&bias[tx * 8]);
    float4 bia1 = *reinterpret_cast<const float4*>(&bias[tx * 8 + 4]);
#pragma unroll
    for (int r = 0; r < 8; r++) {
        int row = rowBase + ty * 8 + r;
        if (row >= M) continue;
        float4 o0, o1;
        o0.x = acc[r][0] + bia0.x; o0.y = acc[r][1] + bia0.y;
        o0.z = acc[r][2] + bia0.z; o0.w = acc[r][3] + bia0.w;
        o1.x = acc[r][4] + bia1.x; o1.y = acc[r][5] + bia1.y;
        o1.z = acc[r][6] + bia1.z; o1.w = acc[r][7] + bia1.w;
        if (RELU) {
            o0.x = fmaxf(o0.x, 0.f); o0.y = fmaxf(o0.y, 0.f);
            o0.z = fmaxf(o0.z, 0.f); o0.w = fmaxf(o0.w, 0.f);
            o1.x = fmaxf(o1.x, 0.f); o1.y = fmaxf(o1.y, 0.f);
            o1.z = fmaxf(o1.z, 0.f); o1.w = fmaxf(o1.w, 0.f);
        }
        *reinterpret_cast<float4*>(&g_h[row * DH + tx * 8])     = o0;
        *reinterpret_cast<float4*>(&g_h[row * DH + tx * 8 + 4]) = o1;
        if (POOL) {
            int b = batch[row];
            red4(&g_pool[b * DH + tx * 8],     o0);
            red4(&g_pool[b * DH + tx * 8 + 4], o1);
        }
    }
}

// ---------------- head: out[g][o] = dot(pool[g]/cnt[g], Wg[o]) + bg[o] ------
__global__ void final_kernel(const float* __restrict__ Wg,
                             const float* __restrict__ bg,
                             float* __restrict__ out) {
    int g = blockIdx.x;
    int lane = threadIdx.x;
    float4 p = reinterpret_cast<const float4*>(g_pool)[g * 32 + lane];
    float c = fmaxf(g_cnt[g], 1.0f);
#pragma unroll
    for (int o = 0; o < 10; o++) {
        float4 w = reinterpret_cast<const float4*>(Wg)[o * 32 + lane];
        float s = p.x * w.x + p.y * w.y + p.z * w.z + p.w * w.w;
#pragma unroll
        for (int off = 16; off; off >>= 1) s += __shfl_xor_sync(0xffffffffu, s, off);
        if (lane == 0) out[g * 10 + o] = s / c + bg[o];
    }
}

// ---------------- launch ----------------------------------------------------
extern "C" void kernel_launch(void* const* d_in, const int* in_sizes, int n_in,
                              void* d_out, int out_size) {
    const float* x     = (const float*)d_in[0];
    const int*   ei    = (const int*)d_in[1];      // int32 (JAX x64 disabled)
    const int*   batch = (const int*)d_in[2];
    const float* W0 = (const float*)d_in[3];
    const float* b0 = (const float*)d_in[4];
    const float* W1 = (const float*)d_in[5];
    const float* b1 = (const float*)d_in[6];
    const float* W2 = (const float*)d_in[7];
    const float* b2 = (const float*)d_in[8];
    const float* Wg = (const float*)d_in[9];
    const float* bg = (const float*)d_in[10];
    float* out = (float*)d_out;

    const int N = in_sizes[0] / DH;     // 100000
    const int E = in_sizes[1] / 2;      // 1600000

    const int gemm_grid = (N + GBM - 1) / GBM;
    const int gat_grid  = (N + 7) / 8;  // 8 warps/block, 1 node/warp

    // CSR build + init (amortized over 3 aggregations)
    init_kernel<<<(NGRAPH * DH > N ? NGRAPH * DH : N) / 512 + 1, 512>>>(N);
    hist_kernel<<<(E + 511) / 512, 512>>>(ei, E);
    scan_kernel<<<1, 1024>>>(N);
    fill_kernel<<<(E + 511) / 512, 512>>>(ei, E);
    count_kernel<<<(N + 255) / 256, 256>>>(batch, N);

    // layer 0
    gather_kernel<true><<<gat_grid, 256>>>(x, N);
    gemm_kernel<true, false><<<gemm_grid, 256>>>(W0, b0, nullptr, N);
    // layer 1
    gather_kernel<false><<<gat_grid, 256>>>(nullptr, N);
    gemm_kernel<true, false><<<gemm_grid, 256>>>(W1, b1, nullptr, N);
    // layer 2 + fused pooling
    gather_kernel<false><<<gat_grid, 256>>>(nullptr, N);
    gemm_kernel<false, true><<<gemm_grid, 256>>>(W2, b2, batch, N);

    final_kernel<<<NGRAPH, 32>>>(Wg, bg, out);
}